// round 11
// baseline (speedup 1.0000x reference)
#include <cuda_runtime.h>
#include <cuda_fp16.h>
#include <mma.h>

using namespace nvcuda;

#define H      64
#define INF    128
#define NREL   8
#define NMAX   100000
#define EMAX   1600000

// ---- scratch ----
__device__ __align__(128) float   g_h  [NMAX * H];
__device__ __align__(128) __half2 g_hmh[NMAX * (H / 2)];  // hm in fp16 (gather payload)
__device__ __align__(128) float g_ps [NMAX];
__device__ __align__(128) float g_pd [NMAX];
__device__ __align__(128) float g_q  [NREL];
__device__ __align__(128) unsigned g_srcs[EMAX + 8];   // src | (typ<<20), dst-sorted
__device__ __align__(128) int      g_dsts[EMAX];
__device__ __align__(128) float    g_cf  [EMAX];
__device__ __align__(128) uint2    g_mx  [EMAX + 8];   // packed {src|typ, exp(e)} (+pad)
__device__ __align__(128) int g_deg [NMAX];
__device__ __align__(128) int g_cur [NMAX];
__device__ __align__(128) int g_off [NMAX + 1];
__device__ __align__(128) int g_bsum[128];

#define LDA 72   // fp16 leading dim for A tiles (pad vs 64 to break conflicts)

// ---------------------------------------------------------------
// K0 (WMMA): h = relu(x @ W_in + b_in); fused edge-degree histogram.
// (g_deg pre-zeroed by memset node; REDG atomics overlap GEMM staging)
// ---------------------------------------------------------------
__global__ __launch_bounds__(256) void k_input_mma(
    const float* __restrict__ x, const float* __restrict__ W,
    const float* __restrict__ b, const int* __restrict__ dst, int N, int E)
{
    __shared__ __align__(128) char sm[32768];
    __half* As = (__half*)sm;               // [128][LDA]
    __half* Bs = (__half*)(sm + 18432);     // [64][64] row-major (k,n)
    float*  Cs = (float*)sm;                // [128][64]

    int t = threadIdx.x, w = t >> 5;
    int n0 = blockIdx.x * 128;

    // fused histogram (fire-and-forget REDs; overlaps the GEMM below)
    for (int i = blockIdx.x * 256 + t; i < E; i += gridDim.x * 256)
        atomicAdd(&g_deg[dst[i]], 1);

    wmma::fragment<wmma::accumulator, 16, 16, 16, float> acc[4];
    #pragma unroll
    for (int nt = 0; nt < 4; nt++) wmma::fill_fragment(acc[nt], 0.f);

    for (int p = 0; p < 2; p++) {
        __syncthreads();
        for (int i = t; i < 128 * 16; i += 256) {
            int r = i >> 4, c4 = i & 15;
            int node = n0 + r;
            float4 v = make_float4(0.f, 0.f, 0.f, 0.f);
            if (node < N) v = *(const float4*)&x[node * INF + p * 64 + c4 * 4];
            __half2 h0 = __floats2half2_rn(v.x, v.y);
            __half2 h1 = __floats2half2_rn(v.z, v.w);
            uint2 pk; pk.x = *(unsigned*)&h0; pk.y = *(unsigned*)&h1;
            *(uint2*)&As[r * LDA + c4 * 4] = pk;
        }
        for (int i = t; i < 64 * 16; i += 256) {
            int k = i >> 4, c4 = i & 15;
            float4 v = *(const float4*)&W[(p * 64 + k) * 64 + c4 * 4];
            __half2 h0 = __floats2half2_rn(v.x, v.y);
            __half2 h1 = __floats2half2_rn(v.z, v.w);
            uint2 pk; pk.x = *(unsigned*)&h0; pk.y = *(unsigned*)&h1;
            *(uint2*)&Bs[k * 64 + c4 * 4] = pk;
        }
        __syncthreads();
        #pragma unroll
        for (int ks = 0; ks < 4; ks++) {
            wmma::fragment<wmma::matrix_a, 16, 16, 16, __half, wmma::row_major> af;
            wmma::load_matrix_sync(af, As + (w * 16) * LDA + ks * 16, LDA);
            #pragma unroll
            for (int nt = 0; nt < 4; nt++) {
                wmma::fragment<wmma::matrix_b, 16, 16, 16, __half, wmma::row_major> bf;
                wmma::load_matrix_sync(bf, Bs + (ks * 16) * 64 + nt * 16, 64);
                wmma::mma_sync(acc[nt], af, bf, acc[nt]);
            }
        }
    }
    __syncthreads();
    #pragma unroll
    for (int nt = 0; nt < 4; nt++)
        wmma::store_matrix_sync(Cs + (w * 16) * 64 + nt * 16, acc[nt], 64,
                                wmma::mem_row_major);
    __syncthreads();
    for (int i = t; i < 128 * 16; i += 256) {
        int r = i >> 4, c4 = i & 15;
        int node = n0 + r;
        if (node < N) {
            float4 v = *(float4*)&Cs[r * 64 + c4 * 4];
            float4 bb = *(const float4*)&b[c4 * 4];
            float4 o;
            o.x = fmaxf(v.x + bb.x, 0.f);
            o.y = fmaxf(v.y + bb.y, 0.f);
            o.z = fmaxf(v.z + bb.z, 0.f);
            o.w = fmaxf(v.w + bb.w, 0.f);
            *(float4*)&g_h[node * H + c4 * 4] = o;
        }
    }
}

// ---------------------------------------------------------------
// K1 (WMMA): hm = h @ W_msg (fp16 out) + fused pd/ps + fused q (block 0)
// + (layer 0 only) fused counting-sort scatter of the edge list.
// ---------------------------------------------------------------
__global__ __launch_bounds__(256) void k_msg_mma(
    const float* __restrict__ Wm, const float* __restrict__ att,
    const float* __restrict__ rel, const float* __restrict__ Wp,
    const int* __restrict__ src, const int* __restrict__ dst,
    const int* __restrict__ typ, const float* __restrict__ conf,
    int N, int E, int do_scatter)
{
    __shared__ __align__(128) char sm[32768];
    __half* As = (__half*)sm;               // [128][LDA]
    __half* Bs = (__half*)(sm + 18432);     // [64][64]
    float*  Cs = (float*)sm;                // [128][64]

    int t = threadIdx.x, w = t >> 5, lane = t & 31;
    int n0 = blockIdx.x * 128;

    // fused sortscatter (layer 0): overlaps GEMM staging/MMA below
    if (do_scatter) {
        for (int i = blockIdx.x * 256 + t; i < E; i += gridDim.x * 256) {
            int d = dst[i];
            int pos = g_off[d] + atomicAdd(&g_cur[d], 1);
            int tt = min(max(typ[i], 0), NREL - 1);
            g_srcs[pos] = (unsigned)src[i] | ((unsigned)tt << 20);
            g_dsts[pos] = d;
            g_cf[pos]   = 0.1f * __logf(fmaxf(conf[i], 1e-6f));
        }
    }

    // fused k_q: block 0's warps compute per-relation scalar
    if (blockIdx.x == 0 && w < NREL) {
        float acc = 0.f;
        for (int hh = lane; hh < H; hh += 32) {
            float v = 0.f;
            #pragma unroll
            for (int r = 0; r < 16; r++) v += rel[w * 16 + r] * Wp[r * H + hh];
            acc += v * att[2 * H + hh];
        }
        #pragma unroll
        for (int o = 16; o; o >>= 1) acc += __shfl_xor_sync(0xffffffffu, acc, o);
        if (lane == 0) g_q[w] = acc;
    }

    for (int i = t; i < 128 * 16; i += 256) {
        int r = i >> 4, c4 = i & 15;
        int node = n0 + r;
        float4 v = make_float4(0.f, 0.f, 0.f, 0.f);
        if (node < N) v = *(const float4*)&g_h[node * H + c4 * 4];
        __half2 h0 = __floats2half2_rn(v.x, v.y);
        __half2 h1 = __floats2half2_rn(v.z, v.w);
        uint2 pk; pk.x = *(unsigned*)&h0; pk.y = *(unsigned*)&h1;
        *(uint2*)&As[r * LDA + c4 * 4] = pk;
    }
    for (int i = t; i < 64 * 16; i += 256) {
        int k = i >> 4, c4 = i & 15;
        float4 v = *(const float4*)&Wm[k * 64 + c4 * 4];
        __half2 h0 = __floats2half2_rn(v.x, v.y);
        __half2 h1 = __floats2half2_rn(v.z, v.w);
        uint2 pk; pk.x = *(unsigned*)&h0; pk.y = *(unsigned*)&h1;
        *(uint2*)&Bs[k * 64 + c4 * 4] = pk;
    }
    __syncthreads();

    wmma::fragment<wmma::accumulator, 16, 16, 16, float> acc[4];
    #pragma unroll
    for (int nt = 0; nt < 4; nt++) wmma::fill_fragment(acc[nt], 0.f);
    #pragma unroll
    for (int ks = 0; ks < 4; ks++) {
        wmma::fragment<wmma::matrix_a, 16, 16, 16, __half, wmma::row_major> af;
        wmma::load_matrix_sync(af, As + (w * 16) * LDA + ks * 16, LDA);
        #pragma unroll
        for (int nt = 0; nt < 4; nt++) {
            wmma::fragment<wmma::matrix_b, 16, 16, 16, __half, wmma::row_major> bf;
            wmma::load_matrix_sync(bf, Bs + (ks * 16) * 64 + nt * 16, 64);
            wmma::mma_sync(acc[nt], af, bf, acc[nt]);
        }
    }
    __syncthreads();
    #pragma unroll
    for (int nt = 0; nt < 4; nt++)
        wmma::store_matrix_sync(Cs + (w * 16) * 64 + nt * 16, acc[nt], 64,
                                wmma::mem_row_major);
    __syncthreads();

    float ad0 = att[lane],      ad1 = att[lane + 32];
    float as0 = att[64 + lane], as1 = att[96 + lane];
    for (int rr = 0; rr < 16; rr++) {
        int r = w * 16 + rr;
        int node = n0 + r;
        float v0 = Cs[r * 64 + lane];
        float v1 = Cs[r * 64 + 32 + lane];
        float pd = v0 * ad0 + v1 * ad1;
        float ps = v0 * as0 + v1 * as1;
        #pragma unroll
        for (int o = 16; o; o >>= 1) {
            pd += __shfl_xor_sync(0xffffffffu, pd, o);
            ps += __shfl_xor_sync(0xffffffffu, ps, o);
        }
        float u0 = Cs[r * 64 + 2 * lane];
        float u1 = Cs[r * 64 + 2 * lane + 1];
        if (node < N) {
            g_hmh[node * (H / 2) + lane] = __floats2half2_rn(u0, u1);
            if (lane == 0) { g_pd[node] = pd; g_ps[node] = ps; }
        }
    }
}

// ---------------------------------------------------------------
// Prefix-sum of degrees
// ---------------------------------------------------------------
__global__ __launch_bounds__(1024) void k_scan1(int N)
{
    __shared__ int ws[32];
    int t = threadIdx.x, lane = t & 31, w = t >> 5;
    int i = blockIdx.x * 1024 + t;
    int v = (i < N) ? g_deg[i] : 0;
    #pragma unroll
    for (int o = 1; o < 32; o <<= 1) {
        int u = __shfl_up_sync(0xffffffffu, v, o);
        if (lane >= o) v += u;
    }
    if (lane == 31) ws[w] = v;
    __syncthreads();
    if (w == 0) {
        int bsum = ws[lane];
        #pragma unroll
        for (int o = 1; o < 32; o <<= 1) {
            int u = __shfl_up_sync(0xffffffffu, bsum, o);
            if (lane >= o) bsum += u;
        }
        ws[lane] = bsum;
    }
    __syncthreads();
    if (w) v += ws[w - 1];
    if (i < N) g_off[i + 1] = v;
    if (t == 1023) g_bsum[blockIdx.x] = v;
}

__global__ __launch_bounds__(1024) void k_scan23(int N, int nb)
{
    __shared__ int s[128];
    int t = threadIdx.x;
    if (t < 128) s[t] = (t < nb) ? g_bsum[t] : 0;
    __syncthreads();
    #pragma unroll
    for (int o = 1; o < 128; o <<= 1) {
        int v = (t >= o && t < 128) ? s[t - o] : 0;
        __syncthreads();
        if (t < 128) s[t] += v;
        __syncthreads();
    }
    int add = blockIdx.x ? s[blockIdx.x - 1] : 0;
    int i = blockIdx.x * 1024 + t;
    if (i < N) g_off[i + 1] += add;
    if (i == 0) g_off[0] = 0;
}

// ---------------------------------------------------------------
// K_w: edge-parallel logit + exp -> packed {src|typ, exp} meta
// ---------------------------------------------------------------
__global__ __launch_bounds__(256) void k_w(int E)
{
    int i = blockIdx.x * blockDim.x + threadIdx.x;
    if (i >= E) return;
    unsigned p = g_srcs[i];
    int d = g_dsts[i];
    float e = g_pd[d] + g_ps[p & 0xFFFFF] + g_q[p >> 20];
    e = e > 0.f ? e : 0.2f * e;
    e += g_cf[i];
    g_mx[i] = make_uint2(p, __float_as_uint(__expf(e)));
}

// ---------------------------------------------------------------
// K_aggr: warp-per-node gather-sum over packed meta, pipelined,
// fused softmax-normalize + residual + relu + layernorm.
// ---------------------------------------------------------------
__global__ __launch_bounds__(256) void k_aggr(
    const float* __restrict__ bias, const float* __restrict__ lng,
    const float* __restrict__ lnb, float* __restrict__ hout, int N)
{
    int n = (blockIdx.x * blockDim.x + threadIdx.x) >> 5;
    if (n >= N) return;
    int lane = threadIdx.x & 31;
    int half = lane >> 4;
    int l    = lane & 15;
    int beg = g_off[n], end = g_off[n + 1];
    float4 acc = make_float4(0.f, 0.f, 0.f, 0.f);
    float ssum = 0.f;

    int j = beg + half;
    unsigned p0 = 0, p1 = 0;
    float e0 = 0.f, e1 = 0.f;
    if (j < end)     { uint2 m = g_mx[j];     p0 = m.x; e0 = __uint_as_float(m.y); }
    if (j + 2 < end) { uint2 m = g_mx[j + 2]; p1 = m.x; e1 = __uint_as_float(m.y); }
    for (; j + 2 < end; j += 4) {
        uint2 m0 = g_mx[j + 4], m1 = g_mx[j + 6];   // prefetch (padded)
        uint2 r0 = *(const uint2*)&g_hmh[(p0 & 0xFFFFF) * (H/2) + l * 2];
        uint2 r1 = *(const uint2*)&g_hmh[(p1 & 0xFFFFF) * (H/2) + l * 2];
        float2 a0 = __half22float2(*(__half2*)&r0.x);
        float2 b0 = __half22float2(*(__half2*)&r0.y);
        float2 a1 = __half22float2(*(__half2*)&r1.x);
        float2 b1 = __half22float2(*(__half2*)&r1.y);
        acc.x += e0 * a0.x + e1 * a1.x;
        acc.y += e0 * a0.y + e1 * a1.y;
        acc.z += e0 * b0.x + e1 * b1.x;
        acc.w += e0 * b0.y + e1 * b1.y;
        ssum += e0 + e1;
        p0 = m0.x; e0 = __uint_as_float(m0.y);
        p1 = m1.x; e1 = __uint_as_float(m1.y);
    }
    if (j < end) {
        uint2 r = *(const uint2*)&g_hmh[(p0 & 0xFFFFF) * (H/2) + l * 2];
        float2 a = __half22float2(*(__half2*)&r.x);
        float2 b = __half22float2(*(__half2*)&r.y);
        acc.x += e0 * a.x; acc.y += e0 * a.y;
        acc.z += e0 * b.x; acc.w += e0 * b.y;
        ssum += e0;
    }

    acc.x += __shfl_xor_sync(0xffffffffu, acc.x, 16);
    acc.y += __shfl_xor_sync(0xffffffffu, acc.y, 16);
    acc.z += __shfl_xor_sync(0xffffffffu, acc.z, 16);
    acc.w += __shfl_xor_sync(0xffffffffu, acc.w, 16);
    ssum  += __shfl_xor_sync(0xffffffffu, ssum,  16);
    float inv = (ssum > 0.f) ? (1.f / ssum) : 0.f;
    float4 hv = *(const float4*)&g_h[n * H + l * 4];
    float4 bb = *(const float4*)&bias[l * 4];
    float4 u;
    u.x = hv.x + fmaxf(acc.x * inv + bb.x, 0.f);
    u.y = hv.y + fmaxf(acc.y * inv + bb.y, 0.f);
    u.z = hv.z + fmaxf(acc.z * inv + bb.z, 0.f);
    u.w = hv.w + fmaxf(acc.w * inv + bb.w, 0.f);
    float s = u.x + u.y + u.z + u.w;
    #pragma unroll
    for (int o = 16; o; o >>= 1) s += __shfl_xor_sync(0xffffffffu, s, o);
    float mu = s * (1.f / 128.f);
    float4 d4 = make_float4(u.x - mu, u.y - mu, u.z - mu, u.w - mu);
    float vs = d4.x*d4.x + d4.y*d4.y + d4.z*d4.z + d4.w*d4.w;
    #pragma unroll
    for (int o = 16; o; o >>= 1) vs += __shfl_xor_sync(0xffffffffu, vs, o);
    float invs = rsqrtf(vs * (1.f / 128.f) + 1e-5f);
    if (half == 0) {
        float4 g4 = *(const float4*)&lng[l * 4];
        float4 b2 = *(const float4*)&lnb[l * 4];
        float* outp = hout ? hout : g_h;
        float4 o4;
        o4.x = d4.x * invs * g4.x + b2.x;
        o4.y = d4.y * invs * g4.y + b2.y;
        o4.z = d4.z * invs * g4.z + b2.z;
        o4.w = d4.w * invs * g4.w + b2.w;
        *(float4*)&outp[n * H + l * 4] = o4;
    }
}

// ---------------------------------------------------------------
extern "C" void kernel_launch(void* const* d_in, const int* in_sizes, int n_in,
                              void* d_out, int out_size)
{
    const float* x         = (const float*)d_in[0];
    const float* W_in      = (const float*)d_in[1];
    const float* b_in      = (const float*)d_in[2];
    const float* W_msg     = (const float*)d_in[3];
    const float* rel_emb   = (const float*)d_in[4];
    const float* W_relproj = (const float*)d_in[5];
    const float* att_vec   = (const float*)d_in[6];
    const float* bias      = (const float*)d_in[7];
    const float* ln_g      = (const float*)d_in[8];
    const float* ln_b      = (const float*)d_in[9];
    const float* edge_attr = (const float*)d_in[10];
    const int*   edge_index= (const int*)d_in[11];
    const int*   edge_type = (const int*)d_in[12];
    float* out = (float*)d_out;

    int N = in_sizes[0] / INF;
    int E = in_sizes[12];
    int L = in_sizes[7] / H;
    const int* src = edge_index;
    const int* dst = edge_index + E;
    int nb = (N + 1023) / 1024;

    void *deg_p = nullptr, *cur_p = nullptr;
    cudaGetSymbolAddress(&deg_p, g_deg);
    cudaGetSymbolAddress(&cur_p, g_cur);
    cudaMemsetAsync(deg_p, 0, N * sizeof(int));
    cudaMemsetAsync(cur_p, 0, N * sizeof(int));

    k_input_mma<<<(N + 127) / 128, 256>>>(x, W_in, b_in, dst, N, E);  // + hist

    k_scan1<<<nb, 1024>>>(N);
    k_scan23<<<nb, 1024>>>(N, nb);

    for (int l = 0; l < L; l++) {
        k_msg_mma<<<(N + 127) / 128, 256>>>(W_msg + l * H * H,
                                            att_vec + l * 3 * H,
                                            rel_emb + l * NREL * 16,
                                            W_relproj + l * 16 * H,
                                            src, dst, edge_type, edge_attr,
                                            N, E, l == 0);          // + scatter on l==0
        k_w<<<(E + 255) / 256, 256>>>(E);
        k_aggr<<<(N * 32 + 255) / 256, 256>>>(bias + l * H,
                                              ln_g + l * H, ln_b + l * H,
                                              (l == L - 1) ? out : (float*)nullptr,
                                              N);
    }
}

// round 12
// speedup vs baseline: 1.0239x; 1.0239x over previous
#include <cuda_runtime.h>
#include <cuda_fp16.h>
#include <mma.h>

using namespace nvcuda;

#define H      64
#define INF    128
#define NREL   8
#define NMAX   100000
#define EMAX   1600000

// ---- scratch ----
__device__ __align__(128) float   g_h  [NMAX * H];
__device__ __align__(128) __half2 g_hmh[NMAX * (H / 2)];  // hm in fp16 (gather payload)
__device__ __align__(128) float g_ps [NMAX];
__device__ __align__(128) float g_pd [NMAX];
__device__ __align__(128) float g_q  [NREL];
__device__ __align__(128) unsigned g_srcs[EMAX + 8];   // src | (typ<<20), dst-sorted
__device__ __align__(128) int      g_dsts[EMAX];
__device__ __align__(128) float    g_cf  [EMAX];
__device__ __align__(128) uint2    g_mx  [EMAX + 8];   // packed {src|typ, exp(e)} (+pad)
__device__ __align__(128) int g_deg [NMAX];
__device__ __align__(128) int g_cur [NMAX];
__device__ __align__(128) int g_off [NMAX + 1];
__device__ __align__(128) int g_bsum[128];

#define LDA 72   // fp16 leading dim for A tiles (pad vs 64 to break conflicts)

// ---------------------------------------------------------------
// K0 (WMMA): h = relu(x @ W_in + b_in); also zeroes deg/cur slice.
// ---------------------------------------------------------------
__global__ __launch_bounds__(256) void k_input_mma(
    const float* __restrict__ x, const float* __restrict__ W,
    const float* __restrict__ b, int N)
{
    __shared__ __align__(128) char sm[32768];
    __half* As = (__half*)sm;               // [128][LDA]
    __half* Bs = (__half*)(sm + 18432);     // [64][64] row-major (k,n)
    float*  Cs = (float*)sm;                // [128][64]

    int t = threadIdx.x, w = t >> 5;
    int n0 = blockIdx.x * 128;

    // fused: zero sort counters for this block's node slice
    if (t < 128 && n0 + t < N) { g_deg[n0 + t] = 0; g_cur[n0 + t] = 0; }

    wmma::fragment<wmma::accumulator, 16, 16, 16, float> acc[4];
    #pragma unroll
    for (int nt = 0; nt < 4; nt++) wmma::fill_fragment(acc[nt], 0.f);

    for (int p = 0; p < 2; p++) {
        __syncthreads();
        for (int i = t; i < 128 * 16; i += 256) {
            int r = i >> 4, c4 = i & 15;
            int node = n0 + r;
            float4 v = make_float4(0.f, 0.f, 0.f, 0.f);
            if (node < N) v = *(const float4*)&x[node * INF + p * 64 + c4 * 4];
            __half2 h0 = __floats2half2_rn(v.x, v.y);
            __half2 h1 = __floats2half2_rn(v.z, v.w);
            uint2 pk; pk.x = *(unsigned*)&h0; pk.y = *(unsigned*)&h1;
            *(uint2*)&As[r * LDA + c4 * 4] = pk;
        }
        for (int i = t; i < 64 * 16; i += 256) {
            int k = i >> 4, c4 = i & 15;
            float4 v = *(const float4*)&W[(p * 64 + k) * 64 + c4 * 4];
            __half2 h0 = __floats2half2_rn(v.x, v.y);
            __half2 h1 = __floats2half2_rn(v.z, v.w);
            uint2 pk; pk.x = *(unsigned*)&h0; pk.y = *(unsigned*)&h1;
            *(uint2*)&Bs[k * 64 + c4 * 4] = pk;
        }
        __syncthreads();
        #pragma unroll
        for (int ks = 0; ks < 4; ks++) {
            wmma::fragment<wmma::matrix_a, 16, 16, 16, __half, wmma::row_major> af;
            wmma::load_matrix_sync(af, As + (w * 16) * LDA + ks * 16, LDA);
            #pragma unroll
            for (int nt = 0; nt < 4; nt++) {
                wmma::fragment<wmma::matrix_b, 16, 16, 16, __half, wmma::row_major> bf;
                wmma::load_matrix_sync(bf, Bs + (ks * 16) * 64 + nt * 16, 64);
                wmma::mma_sync(acc[nt], af, bf, acc[nt]);
            }
        }
    }
    __syncthreads();
    #pragma unroll
    for (int nt = 0; nt < 4; nt++)
        wmma::store_matrix_sync(Cs + (w * 16) * 64 + nt * 16, acc[nt], 64,
                                wmma::mem_row_major);
    __syncthreads();
    for (int i = t; i < 128 * 16; i += 256) {
        int r = i >> 4, c4 = i & 15;
        int node = n0 + r;
        if (node < N) {
            float4 v = *(float4*)&Cs[r * 64 + c4 * 4];
            float4 bb = *(const float4*)&b[c4 * 4];
            float4 o;
            o.x = fmaxf(v.x + bb.x, 0.f);
            o.y = fmaxf(v.y + bb.y, 0.f);
            o.z = fmaxf(v.z + bb.z, 0.f);
            o.w = fmaxf(v.w + bb.w, 0.f);
            *(float4*)&g_h[node * H + c4 * 4] = o;
        }
    }
}

// ---------------------------------------------------------------
// K1 (WMMA): hm = h @ W_msg (fp16 out) + fused pd/ps + fused q (block 0).
// ---------------------------------------------------------------
__global__ __launch_bounds__(256) void k_msg_mma(
    const float* __restrict__ Wm, const float* __restrict__ att,
    const float* __restrict__ rel, const float* __restrict__ Wp, int N)
{
    __shared__ __align__(128) char sm[32768];
    __half* As = (__half*)sm;               // [128][LDA]
    __half* Bs = (__half*)(sm + 18432);     // [64][64]
    float*  Cs = (float*)sm;                // [128][64]

    int t = threadIdx.x, w = t >> 5, lane = t & 31;
    int n0 = blockIdx.x * 128;

    // fused k_q: block 0's warps compute per-relation scalar
    if (blockIdx.x == 0 && w < NREL) {
        float acc = 0.f;
        for (int hh = lane; hh < H; hh += 32) {
            float v = 0.f;
            #pragma unroll
            for (int r = 0; r < 16; r++) v += rel[w * 16 + r] * Wp[r * H + hh];
            acc += v * att[2 * H + hh];
        }
        #pragma unroll
        for (int o = 16; o; o >>= 1) acc += __shfl_xor_sync(0xffffffffu, acc, o);
        if (lane == 0) g_q[w] = acc;
    }

    for (int i = t; i < 128 * 16; i += 256) {
        int r = i >> 4, c4 = i & 15;
        int node = n0 + r;
        float4 v = make_float4(0.f, 0.f, 0.f, 0.f);
        if (node < N) v = *(const float4*)&g_h[node * H + c4 * 4];
        __half2 h0 = __floats2half2_rn(v.x, v.y);
        __half2 h1 = __floats2half2_rn(v.z, v.w);
        uint2 pk; pk.x = *(unsigned*)&h0; pk.y = *(unsigned*)&h1;
        *(uint2*)&As[r * LDA + c4 * 4] = pk;
    }
    for (int i = t; i < 64 * 16; i += 256) {
        int k = i >> 4, c4 = i & 15;
        float4 v = *(const float4*)&Wm[k * 64 + c4 * 4];
        __half2 h0 = __floats2half2_rn(v.x, v.y);
        __half2 h1 = __floats2half2_rn(v.z, v.w);
        uint2 pk; pk.x = *(unsigned*)&h0; pk.y = *(unsigned*)&h1;
        *(uint2*)&Bs[k * 64 + c4 * 4] = pk;
    }
    __syncthreads();

    wmma::fragment<wmma::accumulator, 16, 16, 16, float> acc[4];
    #pragma unroll
    for (int nt = 0; nt < 4; nt++) wmma::fill_fragment(acc[nt], 0.f);
    #pragma unroll
    for (int ks = 0; ks < 4; ks++) {
        wmma::fragment<wmma::matrix_a, 16, 16, 16, __half, wmma::row_major> af;
        wmma::load_matrix_sync(af, As + (w * 16) * LDA + ks * 16, LDA);
        #pragma unroll
        for (int nt = 0; nt < 4; nt++) {
            wmma::fragment<wmma::matrix_b, 16, 16, 16, __half, wmma::row_major> bf;
            wmma::load_matrix_sync(bf, Bs + (ks * 16) * 64 + nt * 16, 64);
            wmma::mma_sync(acc[nt], af, bf, acc[nt]);
        }
    }
    __syncthreads();
    #pragma unroll
    for (int nt = 0; nt < 4; nt++)
        wmma::store_matrix_sync(Cs + (w * 16) * 64 + nt * 16, acc[nt], 64,
                                wmma::mem_row_major);
    __syncthreads();

    float ad0 = att[lane],      ad1 = att[lane + 32];
    float as0 = att[64 + lane], as1 = att[96 + lane];
    for (int rr = 0; rr < 16; rr++) {
        int r = w * 16 + rr;
        int node = n0 + r;
        float v0 = Cs[r * 64 + lane];
        float v1 = Cs[r * 64 + 32 + lane];
        float pd = v0 * ad0 + v1 * ad1;
        float ps = v0 * as0 + v1 * as1;
        #pragma unroll
        for (int o = 16; o; o >>= 1) {
            pd += __shfl_xor_sync(0xffffffffu, pd, o);
            ps += __shfl_xor_sync(0xffffffffu, ps, o);
        }
        float u0 = Cs[r * 64 + 2 * lane];
        float u1 = Cs[r * 64 + 2 * lane + 1];
        if (node < N) {
            g_hmh[node * (H / 2) + lane] = __floats2half2_rn(u0, u1);
            if (lane == 0) { g_pd[node] = pd; g_ps[node] = ps; }
        }
    }
}

// ---------------------------------------------------------------
// Counting sort of edges by dst
// ---------------------------------------------------------------
__global__ __launch_bounds__(256) void k_hist(const int* __restrict__ dst, int E)
{
    int i = blockIdx.x * blockDim.x + threadIdx.x;
    if (i < E) atomicAdd(&g_deg[dst[i]], 1);
}

__global__ __launch_bounds__(1024) void k_scan1(int N)
{
    __shared__ int ws[32];
    int t = threadIdx.x, lane = t & 31, w = t >> 5;
    int i = blockIdx.x * 1024 + t;
    int v = (i < N) ? g_deg[i] : 0;
    #pragma unroll
    for (int o = 1; o < 32; o <<= 1) {
        int u = __shfl_up_sync(0xffffffffu, v, o);
        if (lane >= o) v += u;
    }
    if (lane == 31) ws[w] = v;
    __syncthreads();
    if (w == 0) {
        int bsum = ws[lane];
        #pragma unroll
        for (int o = 1; o < 32; o <<= 1) {
            int u = __shfl_up_sync(0xffffffffu, bsum, o);
            if (lane >= o) bsum += u;
        }
        ws[lane] = bsum;
    }
    __syncthreads();
    if (w) v += ws[w - 1];
    if (i < N) g_off[i + 1] = v;
    if (t == 1023) g_bsum[blockIdx.x] = v;
}

__global__ __launch_bounds__(1024) void k_scan23(int N, int nb)
{
    __shared__ int s[128];
    int t = threadIdx.x;
    if (t < 128) s[t] = (t < nb) ? g_bsum[t] : 0;
    __syncthreads();
    #pragma unroll
    for (int o = 1; o < 128; o <<= 1) {
        int v = (t >= o && t < 128) ? s[t - o] : 0;
        __syncthreads();
        if (t < 128) s[t] += v;
        __syncthreads();
    }
    int add = blockIdx.x ? s[blockIdx.x - 1] : 0;
    int i = blockIdx.x * 1024 + t;
    if (i < N) g_off[i + 1] += add;
    if (i == 0) g_off[0] = 0;
}

__global__ __launch_bounds__(256) void k_sortscatter(
    const int* __restrict__ src, const int* __restrict__ dst,
    const int* __restrict__ typ, const float* __restrict__ conf, int E)
{
    int i = blockIdx.x * blockDim.x + threadIdx.x;
    if (i >= E) return;
    int d = dst[i];
    int pos = g_off[d] + atomicAdd(&g_cur[d], 1);
    int t = min(max(typ[i], 0), NREL - 1);
    g_srcs[pos] = (unsigned)src[i] | ((unsigned)t << 20);
    g_dsts[pos] = d;
    g_cf[pos]   = 0.1f * __logf(fmaxf(conf[i], 1e-6f));
}

// ---------------------------------------------------------------
// K_w: edge-parallel logit + exp -> packed {src|typ, exp} meta
// ---------------------------------------------------------------
__global__ __launch_bounds__(256) void k_w(int E)
{
    int i = blockIdx.x * blockDim.x + threadIdx.x;
    if (i >= E) return;
    unsigned p = g_srcs[i];
    int d = g_dsts[i];
    float e = g_pd[d] + g_ps[p & 0xFFFFF] + g_q[p >> 20];
    e = e > 0.f ? e : 0.2f * e;
    e += g_cf[i];
    g_mx[i] = make_uint2(p, __float_as_uint(__expf(e)));
}

// ---------------------------------------------------------------
// K_aggr: warp-per-node gather-sum over packed meta, pipelined,
// fused softmax-normalize + residual + relu + layernorm.
// ---------------------------------------------------------------
__global__ __launch_bounds__(256) void k_aggr(
    const float* __restrict__ bias, const float* __restrict__ lng,
    const float* __restrict__ lnb, float* __restrict__ hout, int N)
{
    int n = (blockIdx.x * blockDim.x + threadIdx.x) >> 5;
    if (n >= N) return;
    int lane = threadIdx.x & 31;
    int half = lane >> 4;
    int l    = lane & 15;
    int beg = g_off[n], end = g_off[n + 1];
    float4 acc = make_float4(0.f, 0.f, 0.f, 0.f);
    float ssum = 0.f;

    int j = beg + half;
    unsigned p0 = 0, p1 = 0;
    float e0 = 0.f, e1 = 0.f;
    if (j < end)     { uint2 m = g_mx[j];     p0 = m.x; e0 = __uint_as_float(m.y); }
    if (j + 2 < end) { uint2 m = g_mx[j + 2]; p1 = m.x; e1 = __uint_as_float(m.y); }
    for (; j + 2 < end; j += 4) {
        uint2 m0 = g_mx[j + 4], m1 = g_mx[j + 6];   // prefetch (padded)
        uint2 r0 = *(const uint2*)&g_hmh[(p0 & 0xFFFFF) * (H/2) + l * 2];
        uint2 r1 = *(const uint2*)&g_hmh[(p1 & 0xFFFFF) * (H/2) + l * 2];
        float2 a0 = __half22float2(*(__half2*)&r0.x);
        float2 b0 = __half22float2(*(__half2*)&r0.y);
        float2 a1 = __half22float2(*(__half2*)&r1.x);
        float2 b1 = __half22float2(*(__half2*)&r1.y);
        acc.x += e0 * a0.x + e1 * a1.x;
        acc.y += e0 * a0.y + e1 * a1.y;
        acc.z += e0 * b0.x + e1 * b1.x;
        acc.w += e0 * b0.y + e1 * b1.y;
        ssum += e0 + e1;
        p0 = m0.x; e0 = __uint_as_float(m0.y);
        p1 = m1.x; e1 = __uint_as_float(m1.y);
    }
    if (j < end) {
        uint2 r = *(const uint2*)&g_hmh[(p0 & 0xFFFFF) * (H/2) + l * 2];
        float2 a = __half22float2(*(__half2*)&r.x);
        float2 b = __half22float2(*(__half2*)&r.y);
        acc.x += e0 * a.x; acc.y += e0 * a.y;
        acc.z += e0 * b.x; acc.w += e0 * b.y;
        ssum += e0;
    }

    acc.x += __shfl_xor_sync(0xffffffffu, acc.x, 16);
    acc.y += __shfl_xor_sync(0xffffffffu, acc.y, 16);
    acc.z += __shfl_xor_sync(0xffffffffu, acc.z, 16);
    acc.w += __shfl_xor_sync(0xffffffffu, acc.w, 16);
    ssum  += __shfl_xor_sync(0xffffffffu, ssum,  16);
    float inv = (ssum > 0.f) ? (1.f / ssum) : 0.f;
    float4 hv = *(const float4*)&g_h[n * H + l * 4];
    float4 bb = *(const float4*)&bias[l * 4];
    float4 u;
    u.x = hv.x + fmaxf(acc.x * inv + bb.x, 0.f);
    u.y = hv.y + fmaxf(acc.y * inv + bb.y, 0.f);
    u.z = hv.z + fmaxf(acc.z * inv + bb.z, 0.f);
    u.w = hv.w + fmaxf(acc.w * inv + bb.w, 0.f);
    float s = u.x + u.y + u.z + u.w;
    #pragma unroll
    for (int o = 16; o; o >>= 1) s += __shfl_xor_sync(0xffffffffu, s, o);
    float mu = s * (1.f / 128.f);
    float4 d4 = make_float4(u.x - mu, u.y - mu, u.z - mu, u.w - mu);
    float vs = d4.x*d4.x + d4.y*d4.y + d4.z*d4.z + d4.w*d4.w;
    #pragma unroll
    for (int o = 16; o; o >>= 1) vs += __shfl_xor_sync(0xffffffffu, vs, o);
    float invs = rsqrtf(vs * (1.f / 128.f) + 1e-5f);
    if (half == 0) {
        float4 g4 = *(const float4*)&lng[l * 4];
        float4 b2 = *(const float4*)&lnb[l * 4];
        float* outp = hout ? hout : g_h;
        float4 o4;
        o4.x = d4.x * invs * g4.x + b2.x;
        o4.y = d4.y * invs * g4.y + b2.y;
        o4.z = d4.z * invs * g4.z + b2.z;
        o4.w = d4.w * invs * g4.w + b2.w;
        *(float4*)&outp[n * H + l * 4] = o4;
    }
}

// ---------------------------------------------------------------
extern "C" void kernel_launch(void* const* d_in, const int* in_sizes, int n_in,
                              void* d_out, int out_size)
{
    const float* x         = (const float*)d_in[0];
    const float* W_in      = (const float*)d_in[1];
    const float* b_in      = (const float*)d_in[2];
    const float* W_msg     = (const float*)d_in[3];
    const float* rel_emb   = (const float*)d_in[4];
    const float* W_relproj = (const float*)d_in[5];
    const float* att_vec   = (const float*)d_in[6];
    const float* bias      = (const float*)d_in[7];
    const float* ln_g      = (const float*)d_in[8];
    const float* ln_b      = (const float*)d_in[9];
    const float* edge_attr = (const float*)d_in[10];
    const int*   edge_index= (const int*)d_in[11];
    const int*   edge_type = (const int*)d_in[12];
    float* out = (float*)d_out;

    int N = in_sizes[0] / INF;
    int E = in_sizes[12];
    int L = in_sizes[7] / H;
    const int* src = edge_index;
    const int* dst = edge_index + E;
    int nb = (N + 1023) / 1024;

    k_input_mma<<<(N + 127) / 128, 256>>>(x, W_in, b_in, N);   // + zeroes deg/cur

    k_hist<<<(E + 255) / 256, 256>>>(dst, E);
    k_scan1<<<nb, 1024>>>(N);
    k_scan23<<<nb, 1024>>>(N, nb);
    k_sortscatter<<<(E + 255) / 256, 256>>>(src, dst, edge_type, edge_attr, E);

    for (int l = 0; l < L; l++) {
        k_msg_mma<<<(N + 127) / 128, 256>>>(W_msg + l * H * H,
                                            att_vec + l * 3 * H,
                                            rel_emb + l * NREL * 16,
                                            W_relproj + l * 16 * H, N);
        k_w<<<(E + 255) / 256, 256>>>(E);
        k_aggr<<<(N * 32 + 255) / 256, 256>>>(bias + l * H,
                                              ln_g + l * H, ln_b + l * H,
                                              (l == L - 1) ? out : (float*)nullptr,
                                              N);
    }
}

// round 13
// speedup vs baseline: 1.0382x; 1.0140x over previous
#include <cuda_runtime.h>
#include <cuda_fp16.h>
#include <mma.h>

using namespace nvcuda;

#define H      64
#define INF    128
#define NREL   8
#define NMAX   100000
#define EMAX   1600000

// ---- scratch ----
__device__ __align__(128) float   g_h  [NMAX * H];
__device__ __align__(128) __half2 g_hmh[NMAX * (H / 2)];  // hm in fp16 (gather payload)
__device__ __align__(128) float g_ps [NMAX];
__device__ __align__(128) float g_pd [NMAX];
__device__ __align__(128) float g_q  [NREL];
__device__ __align__(128) unsigned g_srcs[EMAX + 8];   // src | (typ<<20), dst-sorted
__device__ __align__(128) int      g_dsts[EMAX];
__device__ __align__(128) float    g_cf  [EMAX];
__device__ __align__(128) float    g_ex  [EMAX + 8];   // exp(e) (+pad for prefetch)
__device__ __align__(128) int g_deg [NMAX];
__device__ __align__(128) int g_cur [NMAX];
__device__ __align__(128) int g_off [NMAX + 1];
__device__ __align__(128) int g_bsum[128];

#define LDA 72   // fp16 leading dim for A tiles (pad vs 64 to break conflicts)

// ---------------------------------------------------------------
// K0 (WMMA): h = relu(x @ W_in + b_in); also zeroes deg/cur slice.
// ---------------------------------------------------------------
__global__ __launch_bounds__(256) void k_input_mma(
    const float* __restrict__ x, const float* __restrict__ W,
    const float* __restrict__ b, int N)
{
    __shared__ __align__(128) char sm[32768];
    __half* As = (__half*)sm;               // [128][LDA]
    __half* Bs = (__half*)(sm + 18432);     // [64][64] row-major (k,n)
    float*  Cs = (float*)sm;                // [128][64]

    int t = threadIdx.x, w = t >> 5;
    int n0 = blockIdx.x * 128;

    if (t < 128 && n0 + t < N) { g_deg[n0 + t] = 0; g_cur[n0 + t] = 0; }

    wmma::fragment<wmma::accumulator, 16, 16, 16, float> acc[4];
    #pragma unroll
    for (int nt = 0; nt < 4; nt++) wmma::fill_fragment(acc[nt], 0.f);

    for (int p = 0; p < 2; p++) {
        __syncthreads();
        for (int i = t; i < 128 * 16; i += 256) {
            int r = i >> 4, c4 = i & 15;
            int node = n0 + r;
            float4 v = make_float4(0.f, 0.f, 0.f, 0.f);
            if (node < N) v = *(const float4*)&x[node * INF + p * 64 + c4 * 4];
            __half2 h0 = __floats2half2_rn(v.x, v.y);
            __half2 h1 = __floats2half2_rn(v.z, v.w);
            uint2 pk; pk.x = *(unsigned*)&h0; pk.y = *(unsigned*)&h1;
            *(uint2*)&As[r * LDA + c4 * 4] = pk;
        }
        for (int i = t; i < 64 * 16; i += 256) {
            int k = i >> 4, c4 = i & 15;
            float4 v = *(const float4*)&W[(p * 64 + k) * 64 + c4 * 4];
            __half2 h0 = __floats2half2_rn(v.x, v.y);
            __half2 h1 = __floats2half2_rn(v.z, v.w);
            uint2 pk; pk.x = *(unsigned*)&h0; pk.y = *(unsigned*)&h1;
            *(uint2*)&Bs[k * 64 + c4 * 4] = pk;
        }
        __syncthreads();
        #pragma unroll
        for (int ks = 0; ks < 4; ks++) {
            wmma::fragment<wmma::matrix_a, 16, 16, 16, __half, wmma::row_major> af;
            wmma::load_matrix_sync(af, As + (w * 16) * LDA + ks * 16, LDA);
            #pragma unroll
            for (int nt = 0; nt < 4; nt++) {
                wmma::fragment<wmma::matrix_b, 16, 16, 16, __half, wmma::row_major> bf;
                wmma::load_matrix_sync(bf, Bs + (ks * 16) * 64 + nt * 16, 64);
                wmma::mma_sync(acc[nt], af, bf, acc[nt]);
            }
        }
    }
    __syncthreads();
    #pragma unroll
    for (int nt = 0; nt < 4; nt++)
        wmma::store_matrix_sync(Cs + (w * 16) * 64 + nt * 16, acc[nt], 64,
                                wmma::mem_row_major);
    __syncthreads();
    for (int i = t; i < 128 * 16; i += 256) {
        int r = i >> 4, c4 = i & 15;
        int node = n0 + r;
        if (node < N) {
            float4 v = *(float4*)&Cs[r * 64 + c4 * 4];
            float4 bb = *(const float4*)&b[c4 * 4];
            float4 o;
            o.x = fmaxf(v.x + bb.x, 0.f);
            o.y = fmaxf(v.y + bb.y, 0.f);
            o.z = fmaxf(v.z + bb.z, 0.f);
            o.w = fmaxf(v.w + bb.w, 0.f);
            *(float4*)&g_h[node * H + c4 * 4] = o;
        }
    }
}

// ---------------------------------------------------------------
// K1 (WMMA): hm = h @ W_msg (fp16 out) + fused pd/ps + fused q (block 0).
// ---------------------------------------------------------------
__global__ __launch_bounds__(256) void k_msg_mma(
    const float* __restrict__ Wm, const float* __restrict__ att,
    const float* __restrict__ rel, const float* __restrict__ Wp, int N)
{
    __shared__ __align__(128) char sm[32768];
    __half* As = (__half*)sm;               // [128][LDA]
    __half* Bs = (__half*)(sm + 18432);     // [64][64]
    float*  Cs = (float*)sm;                // [128][64]

    int t = threadIdx.x, w = t >> 5, lane = t & 31;
    int n0 = blockIdx.x * 128;

    if (blockIdx.x == 0 && w < NREL) {
        float acc = 0.f;
        for (int hh = lane; hh < H; hh += 32) {
            float v = 0.f;
            #pragma unroll
            for (int r = 0; r < 16; r++) v += rel[w * 16 + r] * Wp[r * H + hh];
            acc += v * att[2 * H + hh];
        }
        #pragma unroll
        for (int o = 16; o; o >>= 1) acc += __shfl_xor_sync(0xffffffffu, acc, o);
        if (lane == 0) g_q[w] = acc;
    }

    for (int i = t; i < 128 * 16; i += 256) {
        int r = i >> 4, c4 = i & 15;
        int node = n0 + r;
        float4 v = make_float4(0.f, 0.f, 0.f, 0.f);
        if (node < N) v = *(const float4*)&g_h[node * H + c4 * 4];
        __half2 h0 = __floats2half2_rn(v.x, v.y);
        __half2 h1 = __floats2half2_rn(v.z, v.w);
        uint2 pk; pk.x = *(unsigned*)&h0; pk.y = *(unsigned*)&h1;
        *(uint2*)&As[r * LDA + c4 * 4] = pk;
    }
    for (int i = t; i < 64 * 16; i += 256) {
        int k = i >> 4, c4 = i & 15;
        float4 v = *(const float4*)&Wm[k * 64 + c4 * 4];
        __half2 h0 = __floats2half2_rn(v.x, v.y);
        __half2 h1 = __floats2half2_rn(v.z, v.w);
        uint2 pk; pk.x = *(unsigned*)&h0; pk.y = *(unsigned*)&h1;
        *(uint2*)&Bs[k * 64 + c4 * 4] = pk;
    }
    __syncthreads();

    wmma::fragment<wmma::accumulator, 16, 16, 16, float> acc[4];
    #pragma unroll
    for (int nt = 0; nt < 4; nt++) wmma::fill_fragment(acc[nt], 0.f);
    #pragma unroll
    for (int ks = 0; ks < 4; ks++) {
        wmma::fragment<wmma::matrix_a, 16, 16, 16, __half, wmma::row_major> af;
        wmma::load_matrix_sync(af, As + (w * 16) * LDA + ks * 16, LDA);
        #pragma unroll
        for (int nt = 0; nt < 4; nt++) {
            wmma::fragment<wmma::matrix_b, 16, 16, 16, __half, wmma::row_major> bf;
            wmma::load_matrix_sync(bf, Bs + (ks * 16) * 64 + nt * 16, 64);
            wmma::mma_sync(acc[nt], af, bf, acc[nt]);
        }
    }
    __syncthreads();
    #pragma unroll
    for (int nt = 0; nt < 4; nt++)
        wmma::store_matrix_sync(Cs + (w * 16) * 64 + nt * 16, acc[nt], 64,
                                wmma::mem_row_major);
    __syncthreads();

    float ad0 = att[lane],      ad1 = att[lane + 32];
    float as0 = att[64 + lane], as1 = att[96 + lane];
    for (int rr = 0; rr < 16; rr++) {
        int r = w * 16 + rr;
        int node = n0 + r;
        float v0 = Cs[r * 64 + lane];
        float v1 = Cs[r * 64 + 32 + lane];
        float pd = v0 * ad0 + v1 * ad1;
        float ps = v0 * as0 + v1 * as1;
        #pragma unroll
        for (int o = 16; o; o >>= 1) {
            pd += __shfl_xor_sync(0xffffffffu, pd, o);
            ps += __shfl_xor_sync(0xffffffffu, ps, o);
        }
        float u0 = Cs[r * 64 + 2 * lane];
        float u1 = Cs[r * 64 + 2 * lane + 1];
        if (node < N) {
            g_hmh[node * (H / 2) + lane] = __floats2half2_rn(u0, u1);
            if (lane == 0) { g_pd[node] = pd; g_ps[node] = ps; }
        }
    }
}

// ---------------------------------------------------------------
// Counting sort of edges by dst
// ---------------------------------------------------------------
__global__ __launch_bounds__(256) void k_hist(const int* __restrict__ dst, int E)
{
    int i = blockIdx.x * blockDim.x + threadIdx.x;
    if (i < E) atomicAdd(&g_deg[dst[i]], 1);
}

__global__ __launch_bounds__(1024) void k_scan1(int N)
{
    __shared__ int ws[32];
    int t = threadIdx.x, lane = t & 31, w = t >> 5;
    int i = blockIdx.x * 1024 + t;
    int v = (i < N) ? g_deg[i] : 0;
    #pragma unroll
    for (int o = 1; o < 32; o <<= 1) {
        int u = __shfl_up_sync(0xffffffffu, v, o);
        if (lane >= o) v += u;
    }
    if (lane == 31) ws[w] = v;
    __syncthreads();
    if (w == 0) {
        int bsum = ws[lane];
        #pragma unroll
        for (int o = 1; o < 32; o <<= 1) {
            int u = __shfl_up_sync(0xffffffffu, bsum, o);
            if (lane >= o) bsum += u;
        }
        ws[lane] = bsum;
    }
    __syncthreads();
    if (w) v += ws[w - 1];
    if (i < N) g_off[i + 1] = v;
    if (t == 1023) g_bsum[blockIdx.x] = v;
}

__global__ __launch_bounds__(1024) void k_scan23(int N, int nb)
{
    __shared__ int s[128];
    int t = threadIdx.x;
    if (t < 128) s[t] = (t < nb) ? g_bsum[t] : 0;
    __syncthreads();
    #pragma unroll
    for (int o = 1; o < 128; o <<= 1) {
        int v = (t >= o && t < 128) ? s[t - o] : 0;
        __syncthreads();
        if (t < 128) s[t] += v;
        __syncthreads();
    }
    int add = blockIdx.x ? s[blockIdx.x - 1] : 0;
    int i = blockIdx.x * 1024 + t;
    if (i < N) g_off[i + 1] += add;
    if (i == 0) g_off[0] = 0;
}

__global__ __launch_bounds__(256) void k_sortscatter(
    const int* __restrict__ src, const int* __restrict__ dst,
    const int* __restrict__ typ, const float* __restrict__ conf, int E)
{
    int i = blockIdx.x * blockDim.x + threadIdx.x;
    if (i >= E) return;
    int d = dst[i];
    int pos = g_off[d] + atomicAdd(&g_cur[d], 1);
    int t = min(max(typ[i], 0), NREL - 1);
    g_srcs[pos] = (unsigned)src[i] | ((unsigned)t << 20);
    g_dsts[pos] = d;
    g_cf[pos]   = 0.1f * __logf(fmaxf(conf[i], 1e-6f));
}

// ---------------------------------------------------------------
// K_w: edge-parallel coalesced logit + exp (R9 form)
// ---------------------------------------------------------------
__global__ __launch_bounds__(256) void k_w(int E)
{
    int i = blockIdx.x * blockDim.x + threadIdx.x;
    if (i >= E) return;
    unsigned p = g_srcs[i];
    int d = g_dsts[i];
    float e = g_pd[d] + g_ps[p & 0xFFFFF] + g_q[p >> 20];
    e = e > 0.f ? e : 0.2f * e;
    e += g_cf[i];
    g_ex[i] = __expf(e);
}

// ---------------------------------------------------------------
// K_aggr: quarter-warp gather (8 lanes/edge row, 4 edges concurrent,
// x2 unroll => 8 gathers in flight/warp), fused softmax-normalize +
// residual + relu + layernorm.
// ---------------------------------------------------------------
__global__ __launch_bounds__(256) void k_aggr(
    const float* __restrict__ bias, const float* __restrict__ lng,
    const float* __restrict__ lnb, float* __restrict__ hout, int N)
{
    int n = (blockIdx.x * blockDim.x + threadIdx.x) >> 5;
    if (n >= N) return;
    int lane = threadIdx.x & 31;
    int q = lane >> 3;     // quarter 0..3 -> edge slot within group of 4
    int l = lane & 7;      // 8 lanes cover one 128B row: uint4 each
    int beg = g_off[n], end = g_off[n + 1];

    float f[8];
    #pragma unroll
    for (int i = 0; i < 8; i++) f[i] = 0.f;
    float ssum = 0.f;

    int j = beg + q;
    unsigned p0 = 0, p1 = 0;
    float e0 = 0.f, e1 = 0.f;
    if (j < end)     { p0 = g_srcs[j];     e0 = g_ex[j]; }
    if (j + 4 < end) { p1 = g_srcs[j + 4]; e1 = g_ex[j + 4]; }
    for (; j + 4 < end; j += 8) {
        // prefetch next meta (arrays padded +8; consumed only if guard holds)
        unsigned np0 = g_srcs[j + 8], np1 = g_srcs[j + 12];
        float    ne0 = g_ex[j + 8],   ne1 = g_ex[j + 12];
        uint4 r0 = *(const uint4*)&g_hmh[(p0 & 0xFFFFF) * (H/2) + l * 4];
        uint4 r1 = *(const uint4*)&g_hmh[(p1 & 0xFFFFF) * (H/2) + l * 4];
        float2 a;
        a = __half22float2(*(__half2*)&r0.x); f[0] += e0*a.x; f[1] += e0*a.y;
        a = __half22float2(*(__half2*)&r0.y); f[2] += e0*a.x; f[3] += e0*a.y;
        a = __half22float2(*(__half2*)&r0.z); f[4] += e0*a.x; f[5] += e0*a.y;
        a = __half22float2(*(__half2*)&r0.w); f[6] += e0*a.x; f[7] += e0*a.y;
        a = __half22float2(*(__half2*)&r1.x); f[0] += e1*a.x; f[1] += e1*a.y;
        a = __half22float2(*(__half2*)&r1.y); f[2] += e1*a.x; f[3] += e1*a.y;
        a = __half22float2(*(__half2*)&r1.z); f[4] += e1*a.x; f[5] += e1*a.y;
        a = __half22float2(*(__half2*)&r1.w); f[6] += e1*a.x; f[7] += e1*a.y;
        ssum += e0 + e1;
        p0 = np0; e0 = ne0; p1 = np1; e1 = ne1;
    }
    if (j < end) {
        uint4 r = *(const uint4*)&g_hmh[(p0 & 0xFFFFF) * (H/2) + l * 4];
        float2 a;
        a = __half22float2(*(__half2*)&r.x); f[0] += e0*a.x; f[1] += e0*a.y;
        a = __half22float2(*(__half2*)&r.y); f[2] += e0*a.x; f[3] += e0*a.y;
        a = __half22float2(*(__half2*)&r.z); f[4] += e0*a.x; f[5] += e0*a.y;
        a = __half22float2(*(__half2*)&r.w); f[6] += e0*a.x; f[7] += e0*a.y;
        ssum += e0;
    }

    // combine the 4 quarters (lanes with equal l end up identical)
    #pragma unroll
    for (int i = 0; i < 8; i++) {
        f[i] += __shfl_xor_sync(0xffffffffu, f[i], 8);
        f[i] += __shfl_xor_sync(0xffffffffu, f[i], 16);
    }
    ssum += __shfl_xor_sync(0xffffffffu, ssum, 8);
    ssum += __shfl_xor_sync(0xffffffffu, ssum, 16);
    float inv = (ssum > 0.f) ? (1.f / ssum) : 0.f;

    // u = h + relu(msg + bias); lane covers cols l*8..l*8+7
    float4 h0 = *(const float4*)&g_h[n * H + l * 8];
    float4 h1 = *(const float4*)&g_h[n * H + l * 8 + 4];
    float4 b0 = *(const float4*)&bias[l * 8];
    float4 b1 = *(const float4*)&bias[l * 8 + 4];
    float u[8];
    u[0] = h0.x + fmaxf(f[0] * inv + b0.x, 0.f);
    u[1] = h0.y + fmaxf(f[1] * inv + b0.y, 0.f);
    u[2] = h0.z + fmaxf(f[2] * inv + b0.z, 0.f);
    u[3] = h0.w + fmaxf(f[3] * inv + b0.w, 0.f);
    u[4] = h1.x + fmaxf(f[4] * inv + b1.x, 0.f);
    u[5] = h1.y + fmaxf(f[5] * inv + b1.y, 0.f);
    u[6] = h1.z + fmaxf(f[6] * inv + b1.z, 0.f);
    u[7] = h1.w + fmaxf(f[7] * inv + b1.w, 0.f);

    // layernorm: warp holds 4x duplicated 64 values -> divide by 256
    float s = ((u[0] + u[1]) + (u[2] + u[3])) + ((u[4] + u[5]) + (u[6] + u[7]));
    #pragma unroll
    for (int o = 16; o; o >>= 1) s += __shfl_xor_sync(0xffffffffu, s, o);
    float mu = s * (1.f / 256.f);
    float d[8], vs = 0.f;
    #pragma unroll
    for (int i = 0; i < 8; i++) { d[i] = u[i] - mu; vs += d[i] * d[i]; }
    #pragma unroll
    for (int o = 16; o; o >>= 1) vs += __shfl_xor_sync(0xffffffffu, vs, o);
    float invs = rsqrtf(vs * (1.f / 256.f) + 1e-5f);
    if (q == 0) {
        float4 g0 = *(const float4*)&lng[l * 8];
        float4 g1 = *(const float4*)&lng[l * 8 + 4];
        float4 c0 = *(const float4*)&lnb[l * 8];
        float4 c1 = *(const float4*)&lnb[l * 8 + 4];
        float* outp = hout ? hout : g_h;
        float4 o0, o1;
        o0.x = d[0] * invs * g0.x + c0.x;
        o0.y = d[1] * invs * g0.y + c0.y;
        o0.z = d[2] * invs * g0.z + c0.z;
        o0.w = d[3] * invs * g0.w + c0.w;
        o1.x = d[4] * invs * g1.x + c1.x;
        o1.y = d[5] * invs * g1.y + c1.y;
        o1.z = d[6] * invs * g1.z + c1.z;
        o1.w = d[7] * invs * g1.w + c1.w;
        *(float4*)&outp[n * H + l * 8]     = o0;
        *(float4*)&outp[n * H + l * 8 + 4] = o1;
    }
}

// ---------------------------------------------------------------
extern "C" void kernel_launch(void* const* d_in, const int* in_sizes, int n_in,
                              void* d_out, int out_size)
{
    const float* x         = (const float*)d_in[0];
    const float* W_in      = (const float*)d_in[1];
    const float* b_in      = (const float*)d_in[2];
    const float* W_msg     = (const float*)d_in[3];
    const float* rel_emb   = (const float*)d_in[4];
    const float* W_relproj = (const float*)d_in[5];
    const float* att_vec   = (const float*)d_in[6];
    const float* bias      = (const float*)d_in[7];
    const float* ln_g      = (const float*)d_in[8];
    const float* ln_b      = (const float*)d_in[9];
    const float* edge_attr = (const float*)d_in[10];
    const int*   edge_index= (const int*)d_in[11];
    const int*   edge_type = (const int*)d_in[12];
    float* out = (float*)d_out;

    int N = in_sizes[0] / INF;
    int E = in_sizes[12];
    int L = in_sizes[7] / H;
    const int* src = edge_index;
    const int* dst = edge_index + E;
    int nb = (N + 1023) / 1024;

    k_input_mma<<<(N + 127) / 128, 256>>>(x, W_in, b_in, N);   // + zeroes deg/cur

    k_hist<<<(E + 255) / 256, 256>>>(dst, E);
    k_scan1<<<nb, 1024>>>(N);
    k_scan23<<<nb, 1024>>>(N, nb);
    k_sortscatter<<<(E + 255) / 256, 256>>>(src, dst, edge_type, edge_attr, E);

    for (int l = 0; l < L; l++) {
        k_msg_mma<<<(N + 127) / 128, 256>>>(W_msg + l * H * H,
                                            att_vec + l * 3 * H,
                                            rel_emb + l * NREL * 16,
                                            W_relproj + l * 16 * H, N);
        k_w<<<(E + 255) / 256, 256>>>(E);
        k_aggr<<<(N * 32 + 255) / 256, 256>>>(bias + l * H,
                                              ln_g + l * H, ln_b + l * H,
                                              (l == L - 1) ? out : (float*)nullptr,
                                              N);
    }
}